// round 14
// baseline (speedup 1.0000x reference)
#include <cuda_runtime.h>

// ----------------------------------------------------------------------------
// Ops_GetPointFeat_spconv: multi-scale 3-NN inverse-distance interpolation.
// Grid-bucketed; ONE WARP per (point, scale); closed-form parallel shell
// enumeration; count-based ring stop; single post-loop REDUX top-3 merge.
// R13: scatter fused into the query kernel behind a flag gate; feature index
// packed into g_bctr.w; float4 gather/store.
//
// Selection = min over 64-bit keys (float_bits(d2)<<32 | index): exactly
// lexicographic (d2, index)  ==  jax.lax.top_k tie-break (lower index wins),
// independent of scan/scatter order. d2 uses the reference's RN op order.
// ----------------------------------------------------------------------------

#define N_POINTS   8192
#define OUT_STRIDE 480
#define CAP        32
#define NCELLS     37440   // 32^3 + 16^3 + 8^3 + 4^3
#define KINF       0xFFFFFFFFFFFFFFFFULL
#define FULL       0xFFFFFFFFu
#define SCAT_CTAS  81      // ceil(20576 / 256)
#define QUERY_CTAS 4096

static __device__ int    g_cnt[NCELLS];
static __device__ float4 g_bctr[CAP * NCELLS];  // slot-major; .w = index bits
static __device__ int    g_flag;                // scatter-done gate

// ---------------------------------------------------------------------------
// k_zero: reset counts + gate flag. Separate launch -> stream-ordered before
// the fused kernel, so the gate can never carry a stale value across replays.
// ---------------------------------------------------------------------------
__global__ void k_zero()
{
    int i = blockIdx.x * 256 + threadIdx.x;
    if (i < NCELLS) g_cnt[i] = 0;
    if (i == 0) g_flag = 0;
}

// ---------------------------------------------------------------------------
// Per-lane candidate scan of one cell. Center + feature-row index come from
// ONE float4 load (index bit-packed in .w).
// ---------------------------------------------------------------------------
__device__ __forceinline__ void scan_cell(int cell, float px, float py, float pz,
                                          unsigned long long& k0,
                                          unsigned long long& k1,
                                          unsigned long long& k2)
{
    int    cnt = __ldg(&g_cnt[cell]);
    float4 q   = __ldg(&g_bctr[cell]);   // slot 0 issued alongside cnt
    cnt = min(cnt, CAP);
    for (int j = 0; j < cnt; j++) {
        if (j > 0) q = __ldg(&g_bctr[j * NCELLS + cell]);
        float dx = __fsub_rn(px, q.x);
        float dy = __fsub_rn(py, q.y);
        float dz = __fsub_rn(pz, q.z);
        float d  = __fadd_rn(__fadd_rn(__fmul_rn(dx, dx), __fmul_rn(dy, dy)),
                             __fmul_rn(dz, dz));
        unsigned long long key =
            ((unsigned long long)__float_as_uint(d) << 32) |
            (unsigned)__float_as_uint(q.w);
        if (key < k2) {
            if (key < k1) {
                k2 = k1;
                if (key < k0) { k1 = k0; k0 = key; }
                else          { k1 = key; }
            } else { k2 = key; }
        }
    }
}

// ---------------------------------------------------------------------------
// Fused kernel. CTAs [0, 81): scatter centers into buckets, then release the
// gate. CTAs [81, 81+4096): one warp per (point, scale) query task; spin on
// the gate (acquire) before touching buckets.
// Deadlock-free: blocks dispatch in ascending bid; wave-1 capacity >> 81, so
// all scatter CTAs are resident before query CTAs can fill the machine.
// ---------------------------------------------------------------------------
__global__ void __launch_bounds__(256)
k_main(const float* __restrict__ pts,
       const int* __restrict__ i1, const int* __restrict__ i2,
       const int* __restrict__ i3, const int* __restrict__ i4,
       const float* __restrict__ f1, const float* __restrict__ f2,
       const float* __restrict__ f3, const float* __restrict__ f4,
       float* __restrict__ out)
{
    if (blockIdx.x < SCAT_CTAS) {
        // ---- scatter phase -------------------------------------------------
        int t = blockIdx.x * 256 + threadIdx.x;
        if (t < 20576) {
            int s, local, G, cellBase; const int* idx;
            if (t < 16000)      { s = 0; local = t;         G = 32; cellBase = 0;     idx = i1; }
            else if (t < 20000) { s = 1; local = t - 16000; G = 16; cellBase = 32768; idx = i2; }
            else if (t < 20512) { s = 2; local = t - 20000; G = 8;  cellBase = 36864; idx = i3; }
            else                { s = 3; local = t - 20512; G = 4;  cellBase = 37376; idx = i4; }

            int ix = idx[local * 4 + 1];
            int iy = idx[local * 4 + 2];
            int iz = idx[local * 4 + 3];

            float sf   = (float)(2 << s);
            float ve   = __fmul_rn(0.015f, sf);
            float off  = __fmul_rn(__fmul_rn(-0.5f, 0.015f), 64.0f);  // -0.48
            float half = __fmul_rn(0.5f, ve);

            float4 c;
            c.x = __fadd_rn(__fadd_rn(__fmul_rn((float)ix, ve), off), half);
            c.y = __fadd_rn(__fadd_rn(__fmul_rn((float)iy, ve), off), half);
            c.z = __fadd_rn(__fadd_rn(__fmul_rn((float)iz, ve), off), half);
            c.w = __uint_as_float((unsigned)local);   // packed feature-row index

            int cell = cellBase + (ix * G + iy) * G + iz;
            int pos  = atomicAdd(&g_cnt[cell], 1);
            if (pos < CAP) g_bctr[pos * NCELLS + cell] = c;
        }
        __syncthreads();
        if (threadIdx.x == 0) {
            __threadfence();                // release this CTA's bucket writes
            atomicAdd(&g_flag, 1);
        }
        return;
    }

    // ---- query phase: wait for all scatter CTAs ---------------------------
    if (threadIdx.x == 0) {
        while (atomicAdd(&g_flag, 0) != SCAT_CTAS) __nanosleep(128);
        __threadfence();                    // acquire
    }
    __syncthreads();

    const int lane = threadIdx.x & 31;
    const int gid  = (blockIdx.x - SCAT_CTAS) * 8 + (threadIdx.x >> 5);
    const int s    = gid >> 13;             // scale (warp-uniform)
    const int p    = gid & (N_POINTS - 1);

    const float px = __ldg(&pts[p * 3 + 0]);
    const float py = __ldg(&pts[p * 3 + 1]);
    const float pz = __ldg(&pts[p * 3 + 2]);

    const int G = 32 >> s;
    int cellBase;
    switch (s) { case 0: cellBase = 0; break; case 1: cellBase = 32768; break;
                 case 2: cellBase = 36864; break; default: cellBase = 37376; }

    const float ve  = __fmul_rn(0.015f, (float)(2 << s));
    const float inv = 1.0f / ve;

    int cx = (int)((px + 0.48f) * inv); cx = min(max(cx, 0), G - 1);
    int cy = (int)((py + 0.48f) * inv); cy = min(max(cy, 0), G - 1);
    int cz = (int)((pz + 0.48f) * inv); cz = min(max(cz, 0), G - 1);

    unsigned long long k0 = KINF, k1 = KINF, k2 = KINF;   // per-lane sorted top-3

    for (int r = 1; r <= G; r++) {
        if (r == 1) {
            if (lane < 27) {
                int x = cx + lane / 9 - 1;
                int y = cy + (lane / 3) % 3 - 1;
                int z = cz + lane % 3 - 1;
                if (((unsigned)x < (unsigned)G) & ((unsigned)y < (unsigned)G) &
                    ((unsigned)z < (unsigned)G))
                    scan_cell(cellBase + (x * G + y) * G + z, px, py, pz, k0, k1, k2);
            }
        } else {
            // unclipped shell: 2 x-faces (W^2), 2 y-strips (Wm*W), 2 z-caps (Wm^2)
            const int W  = 2 * r + 1;
            const int Wm = 2 * r - 1;
            const int F  = W * W;
            const int S  = Wm * W;
            const int E  = Wm * Wm;
            const int total = 2 * F + 2 * S + 2 * E;   // 24r^2 + 2
            for (int q = lane; q < total; q += 32) {
                int dx, dy, dz, rem;
                if (q < 2 * F) {                        // x = +-r faces
                    dx = (q < F) ? -r : r;
                    rem = (q < F) ? q : q - F;
                    dy = rem / W - r;
                    dz = rem % W - r;
                } else if (q < 2 * F + 2 * S) {         // y = +-r strips
                    rem = q - 2 * F;
                    dy = (rem < S) ? -r : r;
                    if (rem >= S) rem -= S;
                    dx = rem / W - (r - 1);
                    dz = rem % W - r;
                } else {                                // z = +-r caps
                    rem = q - 2 * F - 2 * S;
                    dz = (rem < E) ? -r : r;
                    if (rem >= E) rem -= E;
                    dx = rem / Wm - (r - 1);
                    dy = rem % Wm - (r - 1);
                }
                int x = cx + dx, y = cy + dy, z = cz + dz;
                if (((unsigned)x < (unsigned)G) & ((unsigned)y < (unsigned)G) &
                    ((unsigned)z < (unsigned)G))
                    scan_cell(cellBase + (x * G + y) * G + z, px, py, pz, k0, k1, k2);
            }
        }

        // stop: >=3 warp-wide candidates strictly below the conservative bound
        // (identical decision to "merged 3rd-best < bq").
        float tb = __fmul_rn(__fadd_rn((float)r, 0.5f), ve);
        float bq = __fmul_rn(__fmul_rn(tb, tb), 0.998f);
        unsigned below =
            (unsigned)(__uint_as_float((unsigned)(k0 >> 32)) < bq) +
            (unsigned)(__uint_as_float((unsigned)(k1 >> 32)) < bq) +
            (unsigned)(__uint_as_float((unsigned)(k2 >> 32)) < bq);
        if (__reduce_add_sync(FULL, below) >= 3) break;
    }

    // final warp-wide lexicographic top-3 merge (lane lists are sorted:
    // global i-th min is always some lane's current head).
    unsigned long long m0, m1, m2;
    {
        unsigned long long c0 = k0, c1 = k1, c2 = k2;
        #pragma unroll
        for (int round = 0; round < 3; round++) {
            unsigned hd   = (unsigned)(c0 >> 32);
            unsigned dmin = __reduce_min_sync(FULL, hd);
            unsigned isel = (hd == dmin) ? (unsigned)c0 : 0xFFFFFFFFu;
            unsigned imin = __reduce_min_sync(FULL, isel);
            unsigned long long m = ((unsigned long long)dmin << 32) | imin;
            if (c0 == m) { c0 = c1; c1 = c2; c2 = KINF; }  // unique keys
            if (round == 0) m0 = m; else if (round == 1) m1 = m; else m2 = m;
        }
    }

    // weights — identical RN op order to the passing kernel (all lanes)
    float b0 = __uint_as_float((unsigned)(m0 >> 32));
    float b1 = __uint_as_float((unsigned)(m1 >> 32));
    float b2 = __uint_as_float((unsigned)(m2 >> 32));
    float r0 = __fdiv_rn(1.0f, __fadd_rn(b0, 1e-8f));
    float r1 = __fdiv_rn(1.0f, __fadd_rn(b1, 1e-8f));
    float r2 = __fdiv_rn(1.0f, __fadd_rn(b2, 1e-8f));
    float sm = __fadd_rn(__fadd_rn(r0, r1), r2);
    float w0 = __fdiv_rn(r0, sm);
    float w1 = __fdiv_rn(r1, sm);
    float w2 = __fdiv_rn(r2, sm);
    int   j0 = (int)(unsigned)(m0 & 0xFFFFFFFFu);
    int   j1 = (int)(unsigned)(m1 & 0xFFFFFFFFu);
    int   j2 = (int)(unsigned)(m2 & 0xFFFFFFFFu);

    // fused per-warp gather, float4-vectorized (C % 4 == 0; 16B alignment
    // holds: rows are C*4B with C>=32, out offsets 0/128/384/896 bytes).
    int C; int oOff; const float* f;
    switch (s) {
        case 0:  C = 32;  oOff = 0;   f = f1; break;
        case 1:  C = 64;  oOff = 32;  f = f2; break;
        case 2:  C = 128; oOff = 96;  f = f3; break;
        default: C = 256; oOff = 224; f = f4; break;
    }
    const int C4 = C >> 2;
    const float4* __restrict__ F0 = (const float4*)f + (size_t)j0 * C4;
    const float4* __restrict__ F1 = (const float4*)f + (size_t)j1 * C4;
    const float4* __restrict__ F2 = (const float4*)f + (size_t)j2 * C4;
    float4* o4 = (float4*)(out + p * OUT_STRIDE + oOff);
    for (int c = lane; c < C4; c += 32) {
        float4 a = __ldg(&F0[c]);
        float4 b = __ldg(&F1[c]);
        float4 d = __ldg(&F2[c]);
        float4 v;
        v.x = fmaf(w2, d.x, fmaf(w1, b.x, w0 * a.x));
        v.y = fmaf(w2, d.y, fmaf(w1, b.y, w0 * a.y));
        v.z = fmaf(w2, d.z, fmaf(w1, b.z, w0 * a.z));
        v.w = fmaf(w2, d.w, fmaf(w1, b.w, w0 * a.w));
        o4[c] = v;
    }
}

// ---------------------------------------------------------------------------
extern "C" void kernel_launch(void* const* d_in, const int* in_sizes, int n_in,
                              void* d_out, int out_size)
{
    const float* points   = nullptr;
    const int*   idx[4]   = {nullptr, nullptr, nullptr, nullptr};
    const float* feats[4] = {nullptr, nullptr, nullptr, nullptr};

    for (int i = 0; i < n_in; i++) {
        switch (in_sizes[i]) {
            case 24576:  points   = (const float*)d_in[i]; break; // points [8192,3]
            case 64000:  idx[0]   = (const int*)  d_in[i]; break; // indices1
            case 512000: feats[0] = (const float*)d_in[i]; break; // feats1
            case 16000:  idx[1]   = (const int*)  d_in[i]; break; // indices2
            case 256000: feats[1] = (const float*)d_in[i]; break; // feats2
            case 2048:   idx[2]   = (const int*)  d_in[i]; break; // indices3
            case 65536:  feats[2] = (const float*)d_in[i]; break; // feats3
            case 256:    idx[3]   = (const int*)  d_in[i]; break; // indices4
            case 16384:  feats[3] = (const float*)d_in[i]; break; // feats4
            default: break;                                       // batch_ids unused
        }
    }

    k_zero<<<(NCELLS + 255) / 256, 256>>>();
    k_main<<<SCAT_CTAS + QUERY_CTAS, 256>>>(points,
                                            idx[0], idx[1], idx[2], idx[3],
                                            feats[0], feats[1], feats[2], feats[3],
                                            (float*)d_out);
}

// round 16
// speedup vs baseline: 1.2790x; 1.2790x over previous
#include <cuda_runtime.h>

// ----------------------------------------------------------------------------
// Ops_GetPointFeat_spconv: multi-scale 3-NN inverse-distance interpolation.
// Grid-bucketed; ONE WARP per (point, scale); table-driven parallel shell
// enumeration; count-based ring stop; single post-loop REDUX top-3 merge;
// packed feature index in g_bctr.w; float4 gather.
//
// Selection = min over 64-bit keys (float_bits(d2)<<32 | index): exactly
// lexicographic (d2, index)  ==  jax.lax.top_k tie-break (lower index wins),
// independent of scan/scatter order. d2 uses the reference's RN op order.
// ----------------------------------------------------------------------------

#define N_POINTS   8192
#define OUT_STRIDE 480
#define CAP        32
#define NCELLS     37440   // 32^3 + 16^3 + 8^3 + 4^3
#define KINF       0xFFFFFFFFFFFFFFFFULL
#define FULL       0xFFFFFFFFu

// shell tables for r = 2..8, shell size 24r^2+2
#define TAB_RMAX   8
#define TAB_TOTAL  4886    // 98+218+386+602+866+1178+1538

static __device__ int    g_cnt[NCELLS];
static __device__ float4 g_bctr[CAP * NCELLS];  // slot-major; .w = index bits
static __device__ int    g_tab[TAB_TOTAL];      // packed (dx+64)|(dy+64)<<8|(dz+64)<<16

__device__ __constant__ int c_tabBase[TAB_RMAX + 2] =
    {0, 0, 0, 98, 316, 702, 1304, 2170, 3348, 4886};  // base[r], r=2..8; [9]=end

// ---------------------------------------------------------------------------
// arithmetic shell decode (q-th cell of radius-r shell); used to FILL the
// table and as fallback for r > TAB_RMAX.
// ---------------------------------------------------------------------------
__device__ __forceinline__ void shell_decode(int r, int q, int& dx, int& dy, int& dz)
{
    const int W  = 2 * r + 1;
    const int Wm = 2 * r - 1;
    const int F  = W * W;
    const int S  = Wm * W;
    const int E  = Wm * Wm;
    int rem;
    if (q < 2 * F) {                        // x = +-r faces
        dx = (q < F) ? -r : r;
        rem = (q < F) ? q : q - F;
        dy = rem / W - r;
        dz = rem % W - r;
    } else if (q < 2 * F + 2 * S) {         // y = +-r strips
        rem = q - 2 * F;
        dy = (rem < S) ? -r : r;
        if (rem >= S) rem -= S;
        dx = rem / W - (r - 1);
        dz = rem % W - r;
    } else {                                // z = +-r caps
        rem = q - 2 * F - 2 * S;
        dz = (rem < E) ? -r : r;
        if (rem >= E) rem -= E;
        dx = rem / Wm - (r - 1);
        dy = rem % Wm - (r - 1);
    }
}

// ---------------------------------------------------------------------------
// k_zero: reset counters + (idempotently) fill the shell tables.
// ---------------------------------------------------------------------------
__global__ void k_zero()
{
    int i = blockIdx.x * 256 + threadIdx.x;
    if (i < NCELLS) g_cnt[i] = 0;
    if (i < TAB_TOTAL) {
        // find r for flat index i
        int r = 2;
        while (i >= c_tabBase[r + 1]) r++;
        int dx, dy, dz;
        shell_decode(r, i - c_tabBase[r], dx, dy, dz);
        g_tab[i] = (dx + 64) | ((dy + 64) << 8) | ((dz + 64) << 16);
    }
}

// ---------------------------------------------------------------------------
__global__ void k_scatter(const int* __restrict__ i1, const int* __restrict__ i2,
                          const int* __restrict__ i3, const int* __restrict__ i4)
{
    int t = blockIdx.x * 256 + threadIdx.x;
    if (t >= 20576) return;

    int s, local, G, cellBase; const int* idx;
    if (t < 16000)      { s = 0; local = t;         G = 32; cellBase = 0;     idx = i1; }
    else if (t < 20000) { s = 1; local = t - 16000; G = 16; cellBase = 32768; idx = i2; }
    else if (t < 20512) { s = 2; local = t - 20000; G = 8;  cellBase = 36864; idx = i3; }
    else                { s = 3; local = t - 20512; G = 4;  cellBase = 37376; idx = i4; }

    int ix = idx[local * 4 + 1];
    int iy = idx[local * 4 + 2];
    int iz = idx[local * 4 + 3];

    float sf   = (float)(2 << s);
    float ve   = __fmul_rn(0.015f, sf);
    float off  = __fmul_rn(__fmul_rn(-0.5f, 0.015f), 64.0f);  // -0.48
    float half = __fmul_rn(0.5f, ve);

    float4 c;
    c.x = __fadd_rn(__fadd_rn(__fmul_rn((float)ix, ve), off), half);
    c.y = __fadd_rn(__fadd_rn(__fmul_rn((float)iy, ve), off), half);
    c.z = __fadd_rn(__fadd_rn(__fmul_rn((float)iz, ve), off), half);
    c.w = __uint_as_float((unsigned)local);   // packed feature-row index

    int cell = cellBase + (ix * G + iy) * G + iz;
    int pos  = atomicAdd(&g_cnt[cell], 1);
    if (pos < CAP) g_bctr[pos * NCELLS + cell] = c;
}

// ---------------------------------------------------------------------------
// Per-lane candidate scan of one cell; center + index in ONE float4 load.
// ---------------------------------------------------------------------------
__device__ __forceinline__ void scan_cell(int cell, float px, float py, float pz,
                                          unsigned long long& k0,
                                          unsigned long long& k1,
                                          unsigned long long& k2)
{
    int    cnt = __ldg(&g_cnt[cell]);
    float4 q   = __ldg(&g_bctr[cell]);   // slot 0 issued alongside cnt
    cnt = min(cnt, CAP);
    for (int j = 0; j < cnt; j++) {
        if (j > 0) q = __ldg(&g_bctr[j * NCELLS + cell]);
        float dx = __fsub_rn(px, q.x);
        float dy = __fsub_rn(py, q.y);
        float dz = __fsub_rn(pz, q.z);
        float d  = __fadd_rn(__fadd_rn(__fmul_rn(dx, dx), __fmul_rn(dy, dy)),
                             __fmul_rn(dz, dz));
        unsigned long long key =
            ((unsigned long long)__float_as_uint(d) << 32) |
            (unsigned)__float_as_uint(q.w);
        if (key < k2) {
            if (key < k1) {
                k2 = k1;
                if (key < k0) { k1 = k0; k0 = key; }
                else          { k1 = key; }
            } else { k2 = key; }
        }
    }
}

// ---------------------------------------------------------------------------
// Query: one warp per (point, scale). 32768 warps = 4096 CTAs x 8 warps.
// r=1: direct lane map (27 cells). r=2..8: table-driven decode (1 load + BFE).
// r>8 (essentially never): arithmetic fallback.
// ---------------------------------------------------------------------------
__global__ void __launch_bounds__(256)
k_query(const float* __restrict__ pts,
        const float* __restrict__ f1, const float* __restrict__ f2,
        const float* __restrict__ f3, const float* __restrict__ f4,
        float* __restrict__ out)
{
    const int lane = threadIdx.x & 31;
    const int gid  = blockIdx.x * 8 + (threadIdx.x >> 5);  // 0..32767
    const int s    = gid >> 13;                            // scale (warp-uniform)
    const int p    = gid & (N_POINTS - 1);

    const float px = __ldg(&pts[p * 3 + 0]);
    const float py = __ldg(&pts[p * 3 + 1]);
    const float pz = __ldg(&pts[p * 3 + 2]);

    const int G = 32 >> s;
    int cellBase;
    switch (s) { case 0: cellBase = 0; break; case 1: cellBase = 32768; break;
                 case 2: cellBase = 36864; break; default: cellBase = 37376; }

    const float ve  = __fmul_rn(0.015f, (float)(2 << s));
    const float inv = 1.0f / ve;

    int cx = (int)((px + 0.48f) * inv); cx = min(max(cx, 0), G - 1);
    int cy = (int)((py + 0.48f) * inv); cy = min(max(cy, 0), G - 1);
    int cz = (int)((pz + 0.48f) * inv); cz = min(max(cz, 0), G - 1);

    unsigned long long k0 = KINF, k1 = KINF, k2 = KINF;   // per-lane sorted top-3

    for (int r = 1; r <= G; r++) {
        if (r == 1) {
            if (lane < 27) {
                int x = cx + lane / 9 - 1;          // compile-time divisors: cheap
                int y = cy + (lane / 3) % 3 - 1;
                int z = cz + lane % 3 - 1;
                if (((unsigned)x < (unsigned)G) & ((unsigned)y < (unsigned)G) &
                    ((unsigned)z < (unsigned)G))
                    scan_cell(cellBase + (x * G + y) * G + z, px, py, pz, k0, k1, k2);
            }
        } else if (r <= TAB_RMAX) {
            const int base  = c_tabBase[r];
            const int total = 24 * r * r + 2;
            for (int q = lane; q < total; q += 32) {
                int pk = __ldg(&g_tab[base + q]);
                int x = cx + (pk & 0xFF) - 64;
                int y = cy + ((pk >> 8) & 0xFF) - 64;
                int z = cz + ((pk >> 16) & 0xFF) - 64;
                if (((unsigned)x < (unsigned)G) & ((unsigned)y < (unsigned)G) &
                    ((unsigned)z < (unsigned)G))
                    scan_cell(cellBase + (x * G + y) * G + z, px, py, pz, k0, k1, k2);
            }
        } else {
            const int total = 24 * r * r + 2;
            for (int q = lane; q < total; q += 32) {
                int dx, dy, dz;
                shell_decode(r, q, dx, dy, dz);
                int x = cx + dx, y = cy + dy, z = cz + dz;
                if (((unsigned)x < (unsigned)G) & ((unsigned)y < (unsigned)G) &
                    ((unsigned)z < (unsigned)G))
                    scan_cell(cellBase + (x * G + y) * G + z, px, py, pz, k0, k1, k2);
            }
        }

        // stop: >=3 warp-wide candidates strictly below the conservative bound
        // (identical decision to "merged 3rd-best < bq").
        float tb = __fmul_rn(__fadd_rn((float)r, 0.5f), ve);
        float bq = __fmul_rn(__fmul_rn(tb, tb), 0.998f);
        unsigned below =
            (unsigned)(__uint_as_float((unsigned)(k0 >> 32)) < bq) +
            (unsigned)(__uint_as_float((unsigned)(k1 >> 32)) < bq) +
            (unsigned)(__uint_as_float((unsigned)(k2 >> 32)) < bq);
        if (__reduce_add_sync(FULL, below) >= 3) break;
    }

    // final warp-wide lexicographic top-3 merge (lane lists are sorted:
    // global i-th min is always some lane's current head).
    unsigned long long m0, m1, m2;
    {
        unsigned long long c0 = k0, c1 = k1, c2 = k2;
        #pragma unroll
        for (int round = 0; round < 3; round++) {
            unsigned hd   = (unsigned)(c0 >> 32);
            unsigned dmin = __reduce_min_sync(FULL, hd);
            unsigned isel = (hd == dmin) ? (unsigned)c0 : 0xFFFFFFFFu;
            unsigned imin = __reduce_min_sync(FULL, isel);
            unsigned long long m = ((unsigned long long)dmin << 32) | imin;
            if (c0 == m) { c0 = c1; c1 = c2; c2 = KINF; }  // unique keys
            if (round == 0) m0 = m; else if (round == 1) m1 = m; else m2 = m;
        }
    }

    // weights — identical RN op order to the passing kernel (all lanes)
    float b0 = __uint_as_float((unsigned)(m0 >> 32));
    float b1 = __uint_as_float((unsigned)(m1 >> 32));
    float b2 = __uint_as_float((unsigned)(m2 >> 32));
    float r0 = __fdiv_rn(1.0f, __fadd_rn(b0, 1e-8f));
    float r1 = __fdiv_rn(1.0f, __fadd_rn(b1, 1e-8f));
    float r2 = __fdiv_rn(1.0f, __fadd_rn(b2, 1e-8f));
    float sm = __fadd_rn(__fadd_rn(r0, r1), r2);
    float w0 = __fdiv_rn(r0, sm);
    float w1 = __fdiv_rn(r1, sm);
    float w2 = __fdiv_rn(r2, sm);
    int   j0 = (int)(unsigned)(m0 & 0xFFFFFFFFu);
    int   j1 = (int)(unsigned)(m1 & 0xFFFFFFFFu);
    int   j2 = (int)(unsigned)(m2 & 0xFFFFFFFFu);

    // fused per-warp gather, float4-vectorized (C % 4 == 0; 16B alignment
    // holds: rows are C*4B with C>=32; out offsets 0/128/384/896 bytes).
    int C; int oOff; const float* f;
    switch (s) {
        case 0:  C = 32;  oOff = 0;   f = f1; break;
        case 1:  C = 64;  oOff = 32;  f = f2; break;
        case 2:  C = 128; oOff = 96;  f = f3; break;
        default: C = 256; oOff = 224; f = f4; break;
    }
    const int C4 = C >> 2;
    const float4* __restrict__ F0 = (const float4*)f + (size_t)j0 * C4;
    const float4* __restrict__ F1 = (const float4*)f + (size_t)j1 * C4;
    const float4* __restrict__ F2 = (const float4*)f + (size_t)j2 * C4;
    float4* o4 = (float4*)(out + p * OUT_STRIDE + oOff);
    for (int c = lane; c < C4; c += 32) {
        float4 a = __ldg(&F0[c]);
        float4 b = __ldg(&F1[c]);
        float4 d = __ldg(&F2[c]);
        float4 v;
        v.x = fmaf(w2, d.x, fmaf(w1, b.x, w0 * a.x));
        v.y = fmaf(w2, d.y, fmaf(w1, b.y, w0 * a.y));
        v.z = fmaf(w2, d.z, fmaf(w1, b.z, w0 * a.z));
        v.w = fmaf(w2, d.w, fmaf(w1, b.w, w0 * a.w));
        o4[c] = v;
    }
}

// ---------------------------------------------------------------------------
extern "C" void kernel_launch(void* const* d_in, const int* in_sizes, int n_in,
                              void* d_out, int out_size)
{
    const float* points   = nullptr;
    const int*   idx[4]   = {nullptr, nullptr, nullptr, nullptr};
    const float* feats[4] = {nullptr, nullptr, nullptr, nullptr};

    for (int i = 0; i < n_in; i++) {
        switch (in_sizes[i]) {
            case 24576:  points   = (const float*)d_in[i]; break; // points [8192,3]
            case 64000:  idx[0]   = (const int*)  d_in[i]; break; // indices1
            case 512000: feats[0] = (const float*)d_in[i]; break; // feats1
            case 16000:  idx[1]   = (const int*)  d_in[i]; break; // indices2
            case 256000: feats[1] = (const float*)d_in[i]; break; // feats2
            case 2048:   idx[2]   = (const int*)  d_in[i]; break; // indices3
            case 65536:  feats[2] = (const float*)d_in[i]; break; // feats3
            case 256:    idx[3]   = (const int*)  d_in[i]; break; // indices4
            case 16384:  feats[3] = (const float*)d_in[i]; break; // feats4
            default: break;                                       // batch_ids unused
        }
    }

    k_zero<<<(NCELLS + 255) / 256, 256>>>();
    k_scatter<<<(20576 + 255) / 256, 256>>>(idx[0], idx[1], idx[2], idx[3]);
    k_query<<<4096, 256>>>(points, feats[0], feats[1], feats[2], feats[3],
                           (float*)d_out);
}